// round 5
// baseline (speedup 1.0000x reference)
#include <cuda_runtime.h>

#define BATCH 4
#define DIMC 256
#define MIDC 128
#define HH 128
#define WW 128
#define EPSV 1e-5f

typedef unsigned long long u64;

__device__ __forceinline__ u64 pack2(float lo, float hi) {
    u64 r;
    asm("mov.b64 %0, {%1, %2};" : "=l"(r) : "f"(lo), "f"(hi));
    return r;
}
__device__ __forceinline__ void unpack2(u64 v, float& lo, float& hi) {
    asm("mov.b64 {%0, %1}, %2;" : "=f"(lo), "=f"(hi) : "l"(v));
}
__device__ __forceinline__ void fma2(u64& d, u64 a, u64 b) {
    asm("fma.rn.f32x2 %0, %1, %2, %0;" : "+l"(d) : "l"(a), "l"(b));
}

// Scratch (device globals: allocation-free)
__device__ float g_colmax[BATCH * MIDC * WW];
__device__ float g_rowmax[BATCH * MIDC * HH];
__device__ float g_r[(size_t)BATCH * DIMC * HH * WW];

__global__ void init_max_kernel() {
    int i = blockIdx.x * blockDim.x + threadIdx.x;
    if (i < BATCH * MIDC * WW) {
        g_colmax[i] = 0.f;
        g_rowmax[i] = 0.f;
    }
}

// 3x3 conv (pad=1) + BN + ReLU. Tile: 8 rows x 128 cols, CO=4 couts/block.
// Thread: 2 quads of 4 contiguous pixels (4xx and 64+4xx) x 4 couts.
// mode 0: column max (over h) ; mode 1: row max (over w) ; mode 2: store NCHW.
__global__ __launch_bounds__(128, 5)
void conv3_kernel(const float* __restrict__ in, const float* __restrict__ wgt,
                  const float* __restrict__ gamma, const float* __restrict__ beta,
                  const float* __restrict__ mean, const float* __restrict__ var,
                  int CIN, int COUT, int mode, float* __restrict__ out)
{
    __shared__ float sIn[4 * 10 * 132];          // 4 ci x 10 rows x 132 (halo)
    __shared__ ulonglong2 sWp[4][4][3];          // (dx0,dx1) dup-u64 pairs
    __shared__ u64 sW2[4][4][3];                 // dx2
    __shared__ float sSc[4], sSh[4];
    __shared__ int sMax[4][128];

    const int h0 = blockIdx.x * 8;
    const int co0 = blockIdx.y * 4;
    const int b = blockIdx.z;
    const int xx = threadIdx.x, yy = threadIdx.y;
    const int tid = yy * 16 + xx;
    const int p0 = xx * 4;          // quad 0
    const int p1 = 64 + xx * 4;     // quad 1

    if (tid < 4) {
        int c = co0 + tid;
        float sc = gamma[c] * rsqrtf(var[c] + EPSV);
        sSc[tid] = sc;
        sSh[tid] = beta[c] - mean[c] * sc;
    }
    for (int i = tid; i < 512; i += 128) ((int*)sMax)[i] = 0;
    __syncthreads();

    u64 acc[4][4];  // [co][quad*2 + pair]
#pragma unroll
    for (int co = 0; co < 4; co++)
#pragma unroll
        for (int q = 0; q < 4; q++) acc[co][q] = 0ULL;

    const float* inb = in + (size_t)b * CIN * HH * WW;

    for (int ci0 = 0; ci0 < CIN; ci0 += 4) {
        for (int idx = tid; idx < 5280; idx += 128) {
            int ci = idx / 1320, r = idx % 1320;
            int hh = r / 132, c = r % 132;
            int gh = h0 - 1 + hh, gw = c - 1;
            float v = 0.f;
            if ((unsigned)gh < (unsigned)HH && (unsigned)gw < (unsigned)WW)
                v = inb[(size_t)(ci0 + ci) * HH * WW + gh * WW + gw];
            sIn[idx] = v;
        }
        for (int idx = tid; idx < 144; idx += 128) {
            int co = idx / 36, r = idx % 36, ci = r / 9, k = r % 9;
            int dy = k / 3, dx = k % 3;
            float w = wgt[((size_t)(co0 + co) * CIN + ci0 + ci) * 9 + k] * sSc[co];
            u64 d = pack2(w, w);
            if (dx == 2) sW2[co][ci][dy] = d;
            else ((u64*)&sWp[co][ci][dy])[dx] = d;
        }
        __syncthreads();

        for (int ci = 0; ci < 4; ci++) {
#pragma unroll
            for (int dy = 0; dy < 3; dy++) {
                const float* base = &sIn[ci * 1320 + (yy + dy) * 132];
                const float* rpA = base + p0;
                const float* rpB = base + p1;
                float4 vA = *(const float4*)rpA;
                float2 hA = *(const float2*)(rpA + 4);
                float4 vB = *(const float4*)rpB;
                float2 hB = *(const float2*)(rpB + 4);

                // quadA pairs
                u64 A00 = pack2(vA.x, vA.y), A01 = pack2(vA.z, vA.w);      // dx0
                u64 A10 = pack2(vA.y, vA.z), A11 = pack2(vA.w, hA.x);      // dx1
                u64 A20 = A01,               A21 = pack2(hA.x, hA.y);      // dx2
                // quadB pairs
                u64 B00 = pack2(vB.x, vB.y), B01 = pack2(vB.z, vB.w);
                u64 B10 = pack2(vB.y, vB.z), B11 = pack2(vB.w, hB.x);
                u64 B20 = B01,               B21 = pack2(hB.x, hB.y);

#pragma unroll
                for (int co = 0; co < 4; co++) {
                    ulonglong2 wp = sWp[co][ci][dy];
                    u64 w2 = sW2[co][ci][dy];
                    fma2(acc[co][0], wp.x, A00); fma2(acc[co][1], wp.x, A01);
                    fma2(acc[co][0], wp.y, A10); fma2(acc[co][1], wp.y, A11);
                    fma2(acc[co][0], w2,   A20); fma2(acc[co][1], w2,   A21);
                    fma2(acc[co][2], wp.x, B00); fma2(acc[co][3], wp.x, B01);
                    fma2(acc[co][2], wp.y, B10); fma2(acc[co][3], wp.y, B11);
                    fma2(acc[co][2], w2,   B20); fma2(acc[co][3], w2,   B21);
                }
            }
        }
        __syncthreads();
    }

    if (mode == 2) {
#pragma unroll
        for (int co = 0; co < 4; co++) {
            float v[8];
            unpack2(acc[co][0], v[0], v[1]); unpack2(acc[co][1], v[2], v[3]);
            unpack2(acc[co][2], v[4], v[5]); unpack2(acc[co][3], v[6], v[7]);
            float4 o0, o1;
            o0.x = fmaxf(v[0] + sSh[co], 0.f); o0.y = fmaxf(v[1] + sSh[co], 0.f);
            o0.z = fmaxf(v[2] + sSh[co], 0.f); o0.w = fmaxf(v[3] + sSh[co], 0.f);
            o1.x = fmaxf(v[4] + sSh[co], 0.f); o1.y = fmaxf(v[5] + sSh[co], 0.f);
            o1.z = fmaxf(v[6] + sSh[co], 0.f); o1.w = fmaxf(v[7] + sSh[co], 0.f);
            float* op = &out[((size_t)(b * COUT + co0 + co) * HH + h0 + yy) * WW];
            *(float4*)(op + p0) = o0;
            *(float4*)(op + p1) = o1;
        }
    } else if (mode == 0) {
#pragma unroll
        for (int co = 0; co < 4; co++) {
            float v[8];
            unpack2(acc[co][0], v[0], v[1]); unpack2(acc[co][1], v[2], v[3]);
            unpack2(acc[co][2], v[4], v[5]); unpack2(acc[co][3], v[6], v[7]);
#pragma unroll
            for (int j = 0; j < 4; j++) {
                float y0 = fmaxf(v[j] + sSh[co], 0.f);
                float y1 = fmaxf(v[4 + j] + sSh[co], 0.f);
                atomicMax(&sMax[co][p0 + j], __float_as_int(y0));
                atomicMax(&sMax[co][p1 + j], __float_as_int(y1));
            }
        }
        __syncthreads();
        int* gout = (int*)out;
        for (int i = tid; i < 512; i += 128) {
            int co = i >> 7, w = i & 127;
            atomicMax(&gout[(b * MIDC + co0 + co) * WW + w], sMax[co][w]);
        }
    } else {
#pragma unroll
        for (int co = 0; co < 4; co++) {
            float v[8];
            unpack2(acc[co][0], v[0], v[1]); unpack2(acc[co][1], v[2], v[3]);
            unpack2(acc[co][2], v[4], v[5]); unpack2(acc[co][3], v[6], v[7]);
            float m = v[0];
#pragma unroll
            for (int p = 1; p < 8; p++) m = fmaxf(m, v[p]);
            float y = fmaxf(m + sSh[co], 0.f);
            atomicMax(&sMax[co][yy], __float_as_int(y));
        }
        __syncthreads();
        int* gout = (int*)out;
        if (tid < 32) {
            int co = tid >> 3, h = tid & 7;
            atomicMax(&gout[(b * MIDC + co0 + co) * HH + h0 + h], sMax[co][h]);
        }
    }
}

// Fused merge: r = relu( bn_p(conv3x3(s, p_w)) + bn_c1(conv1x1(x, c1_w)) )
// s[b,c,h,w] = colmax[b,c,w] + rowmax[b,c,h], materialized per-tile in smem.
__global__ __launch_bounds__(128, 5)
void merge_kernel(const float* __restrict__ x,
                  const float* __restrict__ pw, const float* __restrict__ pg,
                  const float* __restrict__ pb, const float* __restrict__ pm,
                  const float* __restrict__ pv,
                  const float* __restrict__ c1w, const float* __restrict__ c1g,
                  const float* __restrict__ c1b, const float* __restrict__ c1m,
                  const float* __restrict__ c1v)
{
    __shared__ float sBuf[4 * 10 * 132];
    __shared__ ulonglong2 sWp[4][4][3];
    __shared__ u64 sW2[4][4][3];
    __shared__ u64 sW1[4][4];
    __shared__ float sScP[4], sScC[4], sSh[4];

    const int h0 = blockIdx.x * 8;
    const int co0 = blockIdx.y * 4;
    const int b = blockIdx.z;
    const int xx = threadIdx.x, yy = threadIdx.y;
    const int tid = yy * 16 + xx;
    const int p0 = xx * 4;
    const int p1 = 64 + xx * 4;

    if (tid < 4) {
        int c = co0 + tid;
        float scp = pg[c] * rsqrtf(pv[c] + EPSV);
        float scc = c1g[c] * rsqrtf(c1v[c] + EPSV);
        sScP[tid] = scp;
        sScC[tid] = scc;
        sSh[tid] = (pb[c] - pm[c] * scp) + (c1b[c] - c1m[c] * scc);
    }
    __syncthreads();

    u64 acc[4][4];
#pragma unroll
    for (int co = 0; co < 4; co++)
#pragma unroll
        for (int q = 0; q < 4; q++) acc[co][q] = 0ULL;

    // ---- Phase A: 1x1 conv over x
    const float* xb = x + (size_t)b * DIMC * HH * WW;
    for (int ci0 = 0; ci0 < DIMC; ci0 += 4) {
        for (int idx = tid; idx < 1024; idx += 128) {
            int ci = idx >> 8, r = idx & 255;
            int hh = r >> 5, w4 = (r & 31) << 2;
            float4 v = *(const float4*)&xb[(size_t)(ci0 + ci) * HH * WW + (h0 + hh) * WW + w4];
            *(float4*)&sBuf[ci * 1024 + hh * 128 + w4] = v;
        }
        if (tid < 16) {
            int co = tid >> 2, ci = tid & 3;
            float w = c1w[(size_t)(co0 + co) * DIMC + ci0 + ci] * sScC[co];
            sW1[co][ci] = pack2(w, w);
        }
        __syncthreads();
        for (int ci = 0; ci < 4; ci++) {
            const float* rp = &sBuf[ci * 1024 + yy * 128];
            float4 vA = *(const float4*)(rp + p0);
            float4 vB = *(const float4*)(rp + p1);
            u64 a0 = pack2(vA.x, vA.y), a1 = pack2(vA.z, vA.w);
            u64 a2 = pack2(vB.x, vB.y), a3 = pack2(vB.z, vB.w);
#pragma unroll
            for (int co = 0; co < 4; co++) {
                u64 wv = sW1[co][ci];
                fma2(acc[co][0], wv, a0); fma2(acc[co][1], wv, a1);
                fma2(acc[co][2], wv, a2); fma2(acc[co][3], wv, a3);
            }
        }
        __syncthreads();
    }

    // ---- Phase B: 3x3 conv over s (materialized tile, boundary zeros in fill)
    for (int ci0 = 0; ci0 < MIDC; ci0 += 4) {
        for (int idx = tid; idx < 5280; idx += 128) {
            int ci = idx / 1320, r = idx % 1320;
            int hh = r / 132, c = r % 132;
            int gh = h0 - 1 + hh, gw = c - 1;
            float v = 0.f;
            if ((unsigned)gh < (unsigned)HH && (unsigned)gw < (unsigned)WW)
                v = g_colmax[(b * MIDC + ci0 + ci) * WW + gw]
                  + g_rowmax[(b * MIDC + ci0 + ci) * HH + gh];
            sBuf[idx] = v;
        }
        for (int idx = tid; idx < 144; idx += 128) {
            int co = idx / 36, r = idx % 36, ci = r / 9, k = r % 9;
            int dy = k / 3, dx = k % 3;
            float w = pw[((size_t)(co0 + co) * MIDC + ci0 + ci) * 9 + k] * sScP[co];
            u64 d = pack2(w, w);
            if (dx == 2) sW2[co][ci][dy] = d;
            else ((u64*)&sWp[co][ci][dy])[dx] = d;
        }
        __syncthreads();

        for (int ci = 0; ci < 4; ci++) {
#pragma unroll
            for (int dy = 0; dy < 3; dy++) {
                const float* base = &sBuf[ci * 1320 + (yy + dy) * 132];
                const float* rpA = base + p0;
                const float* rpB = base + p1;
                float4 vA = *(const float4*)rpA;
                float2 hA = *(const float2*)(rpA + 4);
                float4 vB = *(const float4*)rpB;
                float2 hB = *(const float2*)(rpB + 4);

                u64 A00 = pack2(vA.x, vA.y), A01 = pack2(vA.z, vA.w);
                u64 A10 = pack2(vA.y, vA.z), A11 = pack2(vA.w, hA.x);
                u64 A20 = A01,               A21 = pack2(hA.x, hA.y);
                u64 B00 = pack2(vB.x, vB.y), B01 = pack2(vB.z, vB.w);
                u64 B10 = pack2(vB.y, vB.z), B11 = pack2(vB.w, hB.x);
                u64 B20 = B01,               B21 = pack2(hB.x, hB.y);

#pragma unroll
                for (int co = 0; co < 4; co++) {
                    ulonglong2 wp = sWp[co][ci][dy];
                    u64 w2 = sW2[co][ci][dy];
                    fma2(acc[co][0], wp.x, A00); fma2(acc[co][1], wp.x, A01);
                    fma2(acc[co][0], wp.y, A10); fma2(acc[co][1], wp.y, A11);
                    fma2(acc[co][0], w2,   A20); fma2(acc[co][1], w2,   A21);
                    fma2(acc[co][2], wp.x, B00); fma2(acc[co][3], wp.x, B01);
                    fma2(acc[co][2], wp.y, B10); fma2(acc[co][3], wp.y, B11);
                    fma2(acc[co][2], w2,   B20); fma2(acc[co][3], w2,   B21);
                }
            }
        }
        __syncthreads();
    }

    // epilogue
#pragma unroll
    for (int co = 0; co < 4; co++) {
        float v[8];
        unpack2(acc[co][0], v[0], v[1]); unpack2(acc[co][1], v[2], v[3]);
        unpack2(acc[co][2], v[4], v[5]); unpack2(acc[co][3], v[6], v[7]);
        float4 o0, o1;
        o0.x = fmaxf(v[0] + sSh[co], 0.f); o0.y = fmaxf(v[1] + sSh[co], 0.f);
        o0.z = fmaxf(v[2] + sSh[co], 0.f); o0.w = fmaxf(v[3] + sSh[co], 0.f);
        o1.x = fmaxf(v[4] + sSh[co], 0.f); o1.y = fmaxf(v[5] + sSh[co], 0.f);
        o1.z = fmaxf(v[6] + sSh[co], 0.f); o1.w = fmaxf(v[7] + sSh[co], 0.f);
        float* op = &g_r[((size_t)(b * DIMC + co0 + co) * HH + h0 + yy) * WW];
        *(float4*)(op + p0) = o0;
        *(float4*)(op + p1) = o1;
    }
}

extern "C" void kernel_launch(void* const* d_in, const int* in_sizes, int n_in,
                              void* d_out, int out_size)
{
    const float* x    = (const float*)d_in[0];
    const float* p1w  = (const float*)d_in[1];
    const float* p1g  = (const float*)d_in[2];
    const float* p1b  = (const float*)d_in[3];
    const float* p1m  = (const float*)d_in[4];
    const float* p1v  = (const float*)d_in[5];
    const float* p2w  = (const float*)d_in[6];
    const float* p2g  = (const float*)d_in[7];
    const float* p2b  = (const float*)d_in[8];
    const float* p2m  = (const float*)d_in[9];
    const float* p2v  = (const float*)d_in[10];
    const float* pw   = (const float*)d_in[11];
    const float* pg   = (const float*)d_in[12];
    const float* pb   = (const float*)d_in[13];
    const float* pm   = (const float*)d_in[14];
    const float* pv   = (const float*)d_in[15];
    const float* c1w  = (const float*)d_in[16];
    const float* c1g  = (const float*)d_in[17];
    const float* c1b  = (const float*)d_in[18];
    const float* c1m  = (const float*)d_in[19];
    const float* c1v  = (const float*)d_in[20];
    const float* c2w  = (const float*)d_in[21];
    const float* c2g  = (const float*)d_in[22];
    const float* c2b  = (const float*)d_in[23];
    const float* c2m  = (const float*)d_in[24];
    const float* c2v  = (const float*)d_in[25];

    float* colmax;  cudaGetSymbolAddress((void**)&colmax, g_colmax);
    float* rowmax;  cudaGetSymbolAddress((void**)&rowmax, g_rowmax);
    float* rbuf;    cudaGetSymbolAddress((void**)&rbuf, g_r);

    dim3 blk(16, 8);

    init_max_kernel<<<256, 256>>>();

    conv3_kernel<<<dim3(16, MIDC / 4, BATCH), blk>>>(
        x, p1w, p1g, p1b, p1m, p1v, DIMC, MIDC, 0, colmax);

    conv3_kernel<<<dim3(16, MIDC / 4, BATCH), blk>>>(
        x, p2w, p2g, p2b, p2m, p2v, DIMC, MIDC, 1, rowmax);

    merge_kernel<<<dim3(16, DIMC / 4, BATCH), blk>>>(
        x, pw, pg, pb, pm, pv, c1w, c1g, c1b, c1m, c1v);

    conv3_kernel<<<dim3(16, DIMC / 4, BATCH), blk>>>(
        rbuf, c2w, c2g, c2b, c2m, c2v, DIMC, DIMC, 2, (float*)d_out);
}

// round 6
// speedup vs baseline: 1.0017x; 1.0017x over previous
#include <cuda_runtime.h>

#define BATCH 4
#define DIMC 256
#define MIDC 128
#define HH 128
#define WW 128
#define EPSV 1e-5f

typedef unsigned long long u64;

__device__ __forceinline__ u64 pack2(float lo, float hi) {
    u64 r;
    asm("mov.b64 %0, {%1, %2};" : "=l"(r) : "f"(lo), "f"(hi));
    return r;
}
__device__ __forceinline__ void unpack2(u64 v, float& lo, float& hi) {
    asm("mov.b64 {%0, %1}, %2;" : "=f"(lo), "=f"(hi) : "l"(v));
}
__device__ __forceinline__ void fma2(u64& d, u64 a, u64 b) {
    asm("fma.rn.f32x2 %0, %1, %2, %0;" : "+l"(d) : "l"(a), "l"(b));
}

// Scratch (device globals: allocation-free)
__device__ float g_colmax[BATCH * MIDC * WW];
__device__ float g_rowmax[BATCH * MIDC * HH];
__device__ float g_r[(size_t)BATCH * DIMC * HH * WW];

__global__ void init_max_kernel() {
    int i = blockIdx.x * blockDim.x + threadIdx.x;
    if (i < BATCH * MIDC * WW) {
        g_colmax[i] = 0.f;
        g_rowmax[i] = 0.f;
    }
}

// 3x3 conv (pad=1) + BN + ReLU. Tile: 8 rows x 128 cols, CO=4 couts/block.
// Thread: 2 quads of 4 contiguous pixels (4xx and 64+4xx) x 4 couts.
// mode 0: column max (over h) ; mode 1: row max (over w) ; mode 2: store NCHW.
__global__ __launch_bounds__(128, 5)
void conv3_kernel(const float* __restrict__ in, const float* __restrict__ wgt,
                  const float* __restrict__ gamma, const float* __restrict__ beta,
                  const float* __restrict__ mean, const float* __restrict__ var,
                  int CIN, int COUT, int mode, float* __restrict__ out)
{
    __shared__ float sIn[4 * 10 * 132];          // 4 ci x 10 rows x 132 (halo)
    __shared__ ulonglong2 sWp[4][4][3];          // (dx0,dx1) dup-u64 pairs
    __shared__ u64 sW2[4][4][3];                 // dx2
    __shared__ float sSc[4], sSh[4];
    __shared__ int sMax[4][128];

    const int h0 = blockIdx.x * 8;
    const int co0 = blockIdx.y * 4;
    const int b = blockIdx.z;
    const int xx = threadIdx.x, yy = threadIdx.y;
    const int tid = yy * 16 + xx;
    const int p0 = xx * 4;          // quad 0
    const int p1 = 64 + xx * 4;     // quad 1

    if (tid < 4) {
        int c = co0 + tid;
        float sc = gamma[c] * rsqrtf(var[c] + EPSV);
        sSc[tid] = sc;
        sSh[tid] = beta[c] - mean[c] * sc;
    }
    for (int i = tid; i < 512; i += 128) ((int*)sMax)[i] = 0;
    __syncthreads();

    u64 acc[4][4];  // [co][quad*2 + pair]
#pragma unroll
    for (int co = 0; co < 4; co++)
#pragma unroll
        for (int q = 0; q < 4; q++) acc[co][q] = 0ULL;

    const float* inb = in + (size_t)b * CIN * HH * WW;

    for (int ci0 = 0; ci0 < CIN; ci0 += 4) {
        for (int idx = tid; idx < 5280; idx += 128) {
            int ci = idx / 1320, r = idx % 1320;
            int hh = r / 132, c = r % 132;
            int gh = h0 - 1 + hh, gw = c - 1;
            float v = 0.f;
            if ((unsigned)gh < (unsigned)HH && (unsigned)gw < (unsigned)WW)
                v = inb[(size_t)(ci0 + ci) * HH * WW + gh * WW + gw];
            sIn[idx] = v;
        }
        for (int idx = tid; idx < 144; idx += 128) {
            int co = idx / 36, r = idx % 36, ci = r / 9, k = r % 9;
            int dy = k / 3, dx = k % 3;
            float w = wgt[((size_t)(co0 + co) * CIN + ci0 + ci) * 9 + k] * sSc[co];
            u64 d = pack2(w, w);
            if (dx == 2) sW2[co][ci][dy] = d;
            else ((u64*)&sWp[co][ci][dy])[dx] = d;
        }
        __syncthreads();

        for (int ci = 0; ci < 4; ci++) {
#pragma unroll
            for (int dy = 0; dy < 3; dy++) {
                const float* base = &sIn[ci * 1320 + (yy + dy) * 132];
                const float* rpA = base + p0;
                const float* rpB = base + p1;
                float4 vA = *(const float4*)rpA;
                float2 hA = *(const float2*)(rpA + 4);
                float4 vB = *(const float4*)rpB;
                float2 hB = *(const float2*)(rpB + 4);

                // quadA pairs
                u64 A00 = pack2(vA.x, vA.y), A01 = pack2(vA.z, vA.w);      // dx0
                u64 A10 = pack2(vA.y, vA.z), A11 = pack2(vA.w, hA.x);      // dx1
                u64 A20 = A01,               A21 = pack2(hA.x, hA.y);      // dx2
                // quadB pairs
                u64 B00 = pack2(vB.x, vB.y), B01 = pack2(vB.z, vB.w);
                u64 B10 = pack2(vB.y, vB.z), B11 = pack2(vB.w, hB.x);
                u64 B20 = B01,               B21 = pack2(hB.x, hB.y);

#pragma unroll
                for (int co = 0; co < 4; co++) {
                    ulonglong2 wp = sWp[co][ci][dy];
                    u64 w2 = sW2[co][ci][dy];
                    fma2(acc[co][0], wp.x, A00); fma2(acc[co][1], wp.x, A01);
                    fma2(acc[co][0], wp.y, A10); fma2(acc[co][1], wp.y, A11);
                    fma2(acc[co][0], w2,   A20); fma2(acc[co][1], w2,   A21);
                    fma2(acc[co][2], wp.x, B00); fma2(acc[co][3], wp.x, B01);
                    fma2(acc[co][2], wp.y, B10); fma2(acc[co][3], wp.y, B11);
                    fma2(acc[co][2], w2,   B20); fma2(acc[co][3], w2,   B21);
                }
            }
        }
        __syncthreads();
    }

    if (mode == 2) {
#pragma unroll
        for (int co = 0; co < 4; co++) {
            float v[8];
            unpack2(acc[co][0], v[0], v[1]); unpack2(acc[co][1], v[2], v[3]);
            unpack2(acc[co][2], v[4], v[5]); unpack2(acc[co][3], v[6], v[7]);
            float4 o0, o1;
            o0.x = fmaxf(v[0] + sSh[co], 0.f); o0.y = fmaxf(v[1] + sSh[co], 0.f);
            o0.z = fmaxf(v[2] + sSh[co], 0.f); o0.w = fmaxf(v[3] + sSh[co], 0.f);
            o1.x = fmaxf(v[4] + sSh[co], 0.f); o1.y = fmaxf(v[5] + sSh[co], 0.f);
            o1.z = fmaxf(v[6] + sSh[co], 0.f); o1.w = fmaxf(v[7] + sSh[co], 0.f);
            float* op = &out[((size_t)(b * COUT + co0 + co) * HH + h0 + yy) * WW];
            *(float4*)(op + p0) = o0;
            *(float4*)(op + p1) = o1;
        }
    } else if (mode == 0) {
#pragma unroll
        for (int co = 0; co < 4; co++) {
            float v[8];
            unpack2(acc[co][0], v[0], v[1]); unpack2(acc[co][1], v[2], v[3]);
            unpack2(acc[co][2], v[4], v[5]); unpack2(acc[co][3], v[6], v[7]);
#pragma unroll
            for (int j = 0; j < 4; j++) {
                float y0 = fmaxf(v[j] + sSh[co], 0.f);
                float y1 = fmaxf(v[4 + j] + sSh[co], 0.f);
                atomicMax(&sMax[co][p0 + j], __float_as_int(y0));
                atomicMax(&sMax[co][p1 + j], __float_as_int(y1));
            }
        }
        __syncthreads();
        int* gout = (int*)out;
        for (int i = tid; i < 512; i += 128) {
            int co = i >> 7, w = i & 127;
            atomicMax(&gout[(b * MIDC + co0 + co) * WW + w], sMax[co][w]);
        }
    } else {
#pragma unroll
        for (int co = 0; co < 4; co++) {
            float v[8];
            unpack2(acc[co][0], v[0], v[1]); unpack2(acc[co][1], v[2], v[3]);
            unpack2(acc[co][2], v[4], v[5]); unpack2(acc[co][3], v[6], v[7]);
            float m = v[0];
#pragma unroll
            for (int p = 1; p < 8; p++) m = fmaxf(m, v[p]);
            float y = fmaxf(m + sSh[co], 0.f);
            atomicMax(&sMax[co][yy], __float_as_int(y));
        }
        __syncthreads();
        int* gout = (int*)out;
        if (tid < 32) {
            int co = tid >> 3, h = tid & 7;
            atomicMax(&gout[(b * MIDC + co0 + co) * HH + h0 + h], sMax[co][h]);
        }
    }
}

// Fused merge: r = relu( bn_p(conv3x3(s, p_w)) + bn_c1(conv1x1(x, c1_w)) )
// s[b,c,h,w] = colmax[b,c,w] + rowmax[b,c,h], materialized per-tile in smem.
__global__ __launch_bounds__(128, 5)
void merge_kernel(const float* __restrict__ x,
                  const float* __restrict__ pw, const float* __restrict__ pg,
                  const float* __restrict__ pb, const float* __restrict__ pm,
                  const float* __restrict__ pv,
                  const float* __restrict__ c1w, const float* __restrict__ c1g,
                  const float* __restrict__ c1b, const float* __restrict__ c1m,
                  const float* __restrict__ c1v)
{
    __shared__ float sBuf[4 * 10 * 132];
    __shared__ ulonglong2 sWp[4][4][3];
    __shared__ u64 sW2[4][4][3];
    __shared__ u64 sW1[4][4];
    __shared__ float sScP[4], sScC[4], sSh[4];

    const int h0 = blockIdx.x * 8;
    const int co0 = blockIdx.y * 4;
    const int b = blockIdx.z;
    const int xx = threadIdx.x, yy = threadIdx.y;
    const int tid = yy * 16 + xx;
    const int p0 = xx * 4;
    const int p1 = 64 + xx * 4;

    if (tid < 4) {
        int c = co0 + tid;
        float scp = pg[c] * rsqrtf(pv[c] + EPSV);
        float scc = c1g[c] * rsqrtf(c1v[c] + EPSV);
        sScP[tid] = scp;
        sScC[tid] = scc;
        sSh[tid] = (pb[c] - pm[c] * scp) + (c1b[c] - c1m[c] * scc);
    }
    __syncthreads();

    u64 acc[4][4];
#pragma unroll
    for (int co = 0; co < 4; co++)
#pragma unroll
        for (int q = 0; q < 4; q++) acc[co][q] = 0ULL;

    // ---- Phase A: 1x1 conv over x
    const float* xb = x + (size_t)b * DIMC * HH * WW;
    for (int ci0 = 0; ci0 < DIMC; ci0 += 4) {
        for (int idx = tid; idx < 1024; idx += 128) {
            int ci = idx >> 8, r = idx & 255;
            int hh = r >> 5, w4 = (r & 31) << 2;
            float4 v = *(const float4*)&xb[(size_t)(ci0 + ci) * HH * WW + (h0 + hh) * WW + w4];
            *(float4*)&sBuf[ci * 1024 + hh * 128 + w4] = v;
        }
        if (tid < 16) {
            int co = tid >> 2, ci = tid & 3;
            float w = c1w[(size_t)(co0 + co) * DIMC + ci0 + ci] * sScC[co];
            sW1[co][ci] = pack2(w, w);
        }
        __syncthreads();
        for (int ci = 0; ci < 4; ci++) {
            const float* rp = &sBuf[ci * 1024 + yy * 128];
            float4 vA = *(const float4*)(rp + p0);
            float4 vB = *(const float4*)(rp + p1);
            u64 a0 = pack2(vA.x, vA.y), a1 = pack2(vA.z, vA.w);
            u64 a2 = pack2(vB.x, vB.y), a3 = pack2(vB.z, vB.w);
#pragma unroll
            for (int co = 0; co < 4; co++) {
                u64 wv = sW1[co][ci];
                fma2(acc[co][0], wv, a0); fma2(acc[co][1], wv, a1);
                fma2(acc[co][2], wv, a2); fma2(acc[co][3], wv, a3);
            }
        }
        __syncthreads();
    }

    // ---- Phase B: 3x3 conv over s (materialized tile, boundary zeros in fill)
    for (int ci0 = 0; ci0 < MIDC; ci0 += 4) {
        for (int idx = tid; idx < 5280; idx += 128) {
            int ci = idx / 1320, r = idx % 1320;
            int hh = r / 132, c = r % 132;
            int gh = h0 - 1 + hh, gw = c - 1;
            float v = 0.f;
            if ((unsigned)gh < (unsigned)HH && (unsigned)gw < (unsigned)WW)
                v = g_colmax[(b * MIDC + ci0 + ci) * WW + gw]
                  + g_rowmax[(b * MIDC + ci0 + ci) * HH + gh];
            sBuf[idx] = v;
        }
        for (int idx = tid; idx < 144; idx += 128) {
            int co = idx / 36, r = idx % 36, ci = r / 9, k = r % 9;
            int dy = k / 3, dx = k % 3;
            float w = pw[((size_t)(co0 + co) * MIDC + ci0 + ci) * 9 + k] * sScP[co];
            u64 d = pack2(w, w);
            if (dx == 2) sW2[co][ci][dy] = d;
            else ((u64*)&sWp[co][ci][dy])[dx] = d;
        }
        __syncthreads();

        for (int ci = 0; ci < 4; ci++) {
#pragma unroll
            for (int dy = 0; dy < 3; dy++) {
                const float* base = &sBuf[ci * 1320 + (yy + dy) * 132];
                const float* rpA = base + p0;
                const float* rpB = base + p1;
                float4 vA = *(const float4*)rpA;
                float2 hA = *(const float2*)(rpA + 4);
                float4 vB = *(const float4*)rpB;
                float2 hB = *(const float2*)(rpB + 4);

                u64 A00 = pack2(vA.x, vA.y), A01 = pack2(vA.z, vA.w);
                u64 A10 = pack2(vA.y, vA.z), A11 = pack2(vA.w, hA.x);
                u64 A20 = A01,               A21 = pack2(hA.x, hA.y);
                u64 B00 = pack2(vB.x, vB.y), B01 = pack2(vB.z, vB.w);
                u64 B10 = pack2(vB.y, vB.z), B11 = pack2(vB.w, hB.x);
                u64 B20 = B01,               B21 = pack2(hB.x, hB.y);

#pragma unroll
                for (int co = 0; co < 4; co++) {
                    ulonglong2 wp = sWp[co][ci][dy];
                    u64 w2 = sW2[co][ci][dy];
                    fma2(acc[co][0], wp.x, A00); fma2(acc[co][1], wp.x, A01);
                    fma2(acc[co][0], wp.y, A10); fma2(acc[co][1], wp.y, A11);
                    fma2(acc[co][0], w2,   A20); fma2(acc[co][1], w2,   A21);
                    fma2(acc[co][2], wp.x, B00); fma2(acc[co][3], wp.x, B01);
                    fma2(acc[co][2], wp.y, B10); fma2(acc[co][3], wp.y, B11);
                    fma2(acc[co][2], w2,   B20); fma2(acc[co][3], w2,   B21);
                }
            }
        }
        __syncthreads();
    }

    // epilogue
#pragma unroll
    for (int co = 0; co < 4; co++) {
        float v[8];
        unpack2(acc[co][0], v[0], v[1]); unpack2(acc[co][1], v[2], v[3]);
        unpack2(acc[co][2], v[4], v[5]); unpack2(acc[co][3], v[6], v[7]);
        float4 o0, o1;
        o0.x = fmaxf(v[0] + sSh[co], 0.f); o0.y = fmaxf(v[1] + sSh[co], 0.f);
        o0.z = fmaxf(v[2] + sSh[co], 0.f); o0.w = fmaxf(v[3] + sSh[co], 0.f);
        o1.x = fmaxf(v[4] + sSh[co], 0.f); o1.y = fmaxf(v[5] + sSh[co], 0.f);
        o1.z = fmaxf(v[6] + sSh[co], 0.f); o1.w = fmaxf(v[7] + sSh[co], 0.f);
        float* op = &g_r[((size_t)(b * DIMC + co0 + co) * HH + h0 + yy) * WW];
        *(float4*)(op + p0) = o0;
        *(float4*)(op + p1) = o1;
    }
}

extern "C" void kernel_launch(void* const* d_in, const int* in_sizes, int n_in,
                              void* d_out, int out_size)
{
    const float* x    = (const float*)d_in[0];
    const float* p1w  = (const float*)d_in[1];
    const float* p1g  = (const float*)d_in[2];
    const float* p1b  = (const float*)d_in[3];
    const float* p1m  = (const float*)d_in[4];
    const float* p1v  = (const float*)d_in[5];
    const float* p2w  = (const float*)d_in[6];
    const float* p2g  = (const float*)d_in[7];
    const float* p2b  = (const float*)d_in[8];
    const float* p2m  = (const float*)d_in[9];
    const float* p2v  = (const float*)d_in[10];
    const float* pw   = (const float*)d_in[11];
    const float* pg   = (const float*)d_in[12];
    const float* pb   = (const float*)d_in[13];
    const float* pm   = (const float*)d_in[14];
    const float* pv   = (const float*)d_in[15];
    const float* c1w  = (const float*)d_in[16];
    const float* c1g  = (const float*)d_in[17];
    const float* c1b  = (const float*)d_in[18];
    const float* c1m  = (const float*)d_in[19];
    const float* c1v  = (const float*)d_in[20];
    const float* c2w  = (const float*)d_in[21];
    const float* c2g  = (const float*)d_in[22];
    const float* c2b  = (const float*)d_in[23];
    const float* c2m  = (const float*)d_in[24];
    const float* c2v  = (const float*)d_in[25];

    float* colmax;  cudaGetSymbolAddress((void**)&colmax, g_colmax);
    float* rowmax;  cudaGetSymbolAddress((void**)&rowmax, g_rowmax);
    float* rbuf;    cudaGetSymbolAddress((void**)&rbuf, g_r);

    dim3 blk(16, 8);

    init_max_kernel<<<256, 256>>>();

    conv3_kernel<<<dim3(16, MIDC / 4, BATCH), blk>>>(
        x, p1w, p1g, p1b, p1m, p1v, DIMC, MIDC, 0, colmax);

    conv3_kernel<<<dim3(16, MIDC / 4, BATCH), blk>>>(
        x, p2w, p2g, p2b, p2m, p2v, DIMC, MIDC, 1, rowmax);

    merge_kernel<<<dim3(16, DIMC / 4, BATCH), blk>>>(
        x, pw, pg, pb, pm, pv, c1w, c1g, c1b, c1m, c1v);

    conv3_kernel<<<dim3(16, DIMC / 4, BATCH), blk>>>(
        rbuf, c2w, c2g, c2b, c2m, c2v, DIMC, DIMC, 2, (float*)d_out);
}

// round 7
// speedup vs baseline: 1.4020x; 1.3996x over previous
#include <cuda_runtime.h>
#include <cstdint>

#define BATCH 4
#define DIMC 256
#define MIDC 128
#define HH 128
#define WW 128
#define EPSV 1e-5f

typedef unsigned long long u64;

__device__ __forceinline__ u64 pack2(float lo, float hi) {
    u64 r;
    asm("mov.b64 %0, {%1, %2};" : "=l"(r) : "f"(lo), "f"(hi));
    return r;
}
__device__ __forceinline__ void unpack2(u64 v, float& lo, float& hi) {
    asm("mov.b64 {%0, %1}, %2;" : "=f"(lo), "=f"(hi) : "l"(v));
}
__device__ __forceinline__ void fma2(u64& d, u64 a, u64 b) {
    asm("fma.rn.f32x2 %0, %1, %2, %0;" : "+l"(d) : "l"(a), "l"(b));
}
__device__ __forceinline__ uint32_t smem_u32(const void* p) {
    return (uint32_t)__cvta_generic_to_shared(p);
}
__device__ __forceinline__ void cp4(uint32_t d, const void* s, bool valid) {
    int sz = valid ? 4 : 0;
    asm volatile("cp.async.ca.shared.global [%0], [%1], 4, %2;" :: "r"(d), "l"(s), "r"(sz));
}
__device__ __forceinline__ void cp16(uint32_t d, const void* s) {
    asm volatile("cp.async.cg.shared.global [%0], [%1], 16;" :: "r"(d), "l"(s));
}
__device__ __forceinline__ void cp_commit() { asm volatile("cp.async.commit_group;"); }
__device__ __forceinline__ void cp_wait0() { asm volatile("cp.async.wait_group 0;"); }

// Scratch (device globals: allocation-free)
__device__ float g_colmax[BATCH * MIDC * WW];
__device__ float g_rowmax[BATCH * MIDC * HH];
__device__ float g_r[(size_t)BATCH * DIMC * HH * WW];

__global__ void init_max_kernel() {
    int i = blockIdx.x * blockDim.x + threadIdx.x;
    if (i < BATCH * MIDC * WW) {
        g_colmax[i] = 0.f;
        g_rowmax[i] = 0.f;
    }
}

// 3x3 conv (pad=1) + BN + ReLU. Tile 8h x 64w, CO=8 couts/block.
// Thread: pixel pairs (2xx,2xx+1) and (32+2xx,33+2xx), 8 couts -> 16 u64 acc.
// mode 0: col max (over h); mode 1: row max (over w); mode 2: store NCHW.
__global__ __launch_bounds__(128, 4)
void conv3_kernel(const float* __restrict__ in, const float* __restrict__ wgt,
                  const float* __restrict__ gamma, const float* __restrict__ beta,
                  const float* __restrict__ mean, const float* __restrict__ var,
                  int CIN, int COUT, int mode, float* __restrict__ out)
{
    __shared__ float sIn[2][4][10][66];     // double-buffered input tile
    __shared__ float sWraw[2][288];         // raw weights (cp.async)
    __shared__ ulonglong2 sWp[8][4][3];     // dup pairs (dx0,dx1)
    __shared__ u64 sW2[8][4][3];            // dup dx2
    __shared__ float sSc[8], sSh[8];
    __shared__ int sMax[8][64];

    const int wt = blockIdx.x & 1, ht = blockIdx.x >> 1;
    const int w0 = wt * 64, h0 = ht * 8;
    const int co0 = blockIdx.y * 8;
    const int b = blockIdx.z;
    const int xx = threadIdx.x, yy = threadIdx.y;
    const int tid = yy * 16 + xx;

    if (tid < 8) {
        int c = co0 + tid;
        float sc = gamma[c] * rsqrtf(var[c] + EPSV);
        sSc[tid] = sc;
        sSh[tid] = beta[c] - mean[c] * sc;
    }
    for (int i = tid; i < 512; i += 128) ((int*)sMax)[i] = 0;

    const float* inb = in + (size_t)b * CIN * HH * WW;
    const int nch = CIN / 4;

    // ---- staging helper (inlined twice via lambda-ish macro) ----
    auto stage = [&](int buf, int ci0) {
        for (int idx = tid; idx < 2640; idx += 128) {
            int ci = idx / 660, r = idx % 660;
            int hh = r / 66, c = r % 66;
            int gh = h0 - 1 + hh, gw = w0 - 1 + c;
            bool valid = ((unsigned)gh < (unsigned)HH) && ((unsigned)gw < (unsigned)WW);
            int ghc = valid ? gh : 0, gwc = valid ? gw : 0;
            cp4(smem_u32(&sIn[buf][ci][hh][c]),
                inb + (size_t)(ci0 + ci) * HH * WW + ghc * WW + gwc, valid);
        }
        if (tid < 72) {
            int co = tid / 9, q = tid % 9;
            cp16(smem_u32(&sWraw[buf][co * 36 + q * 4]),
                 wgt + ((size_t)(co0 + co) * CIN + ci0) * 9 + q * 4);
        }
    };

    stage(0, 0);
    cp_commit();

    u64 acc[8][2];
#pragma unroll
    for (int co = 0; co < 8; co++) { acc[co][0] = 0ULL; acc[co][1] = 0ULL; }

    for (int ch = 0; ch < nch; ch++) {
        int buf = ch & 1;
        cp_wait0();
        __syncthreads();
        if (ch + 1 < nch) { stage(buf ^ 1, (ch + 1) * 4); cp_commit(); }

        // expand weights: raw * bn_scale, duplicated halves
        for (int idx = tid; idx < 288; idx += 128) {
            int co = idx / 36, r = idx % 36, ci = r / 9, k = r % 9;
            int dy = k / 3, dx = k % 3;
            float w = sWraw[buf][idx] * sSc[co];
            u64 d = pack2(w, w);
            if (dx == 2) sW2[co][ci][dy] = d;
            else ((u64*)&sWp[co][ci][dy])[dx] = d;
        }
        __syncthreads();

        for (int ci = 0; ci < 4; ci++) {
#pragma unroll
            for (int dy = 0; dy < 3; dy++) {
                const float* row = &sIn[buf][ci][yy + dy][0];
                u64 P0 = *(const u64*)(row + 2 * xx);        // cols 2xx,2xx+1
                u64 P2 = *(const u64*)(row + 2 * xx + 2);    // cols 2xx+2,2xx+3
                u64 Q0 = *(const u64*)(row + 2 * xx + 32);
                u64 Q2 = *(const u64*)(row + 2 * xx + 34);
                float p0l, p0h, p2l, p2h, q0l, q0h, q2l, q2h;
                unpack2(P0, p0l, p0h); unpack2(P2, p2l, p2h);
                unpack2(Q0, q0l, q0h); unpack2(Q2, q2l, q2h);
                u64 P1 = pack2(p0h, p2l);
                u64 Q1 = pack2(q0h, q2l);
#pragma unroll
                for (int co = 0; co < 8; co++) {
                    ulonglong2 wp = sWp[co][ci][dy];
                    u64 w2v = sW2[co][ci][dy];
                    fma2(acc[co][0], wp.x, P0);
                    fma2(acc[co][1], wp.x, Q0);
                    fma2(acc[co][0], wp.y, P1);
                    fma2(acc[co][1], wp.y, Q1);
                    fma2(acc[co][0], w2v, P2);
                    fma2(acc[co][1], w2v, Q2);
                }
            }
        }
    }

    // epilogue: pixels w0+2xx, w0+2xx+1 (acc[co][0]) and +32 (acc[co][1])
    if (mode == 2) {
#pragma unroll
        for (int co = 0; co < 8; co++) {
            float v0, v1, v2, v3;
            unpack2(acc[co][0], v0, v1);
            unpack2(acc[co][1], v2, v3);
            float2 oA, oB;
            oA.x = fmaxf(v0 + sSh[co], 0.f); oA.y = fmaxf(v1 + sSh[co], 0.f);
            oB.x = fmaxf(v2 + sSh[co], 0.f); oB.y = fmaxf(v3 + sSh[co], 0.f);
            float* op = &out[((size_t)(b * COUT + co0 + co) * HH + h0 + yy) * WW + w0];
            *(float2*)(op + 2 * xx) = oA;
            *(float2*)(op + 2 * xx + 32) = oB;
        }
    } else if (mode == 0) {
#pragma unroll
        for (int co = 0; co < 8; co++) {
            float v0, v1, v2, v3;
            unpack2(acc[co][0], v0, v1);
            unpack2(acc[co][1], v2, v3);
            atomicMax(&sMax[co][2 * xx],      __float_as_int(fmaxf(v0 + sSh[co], 0.f)));
            atomicMax(&sMax[co][2 * xx + 1],  __float_as_int(fmaxf(v1 + sSh[co], 0.f)));
            atomicMax(&sMax[co][2 * xx + 32], __float_as_int(fmaxf(v2 + sSh[co], 0.f)));
            atomicMax(&sMax[co][2 * xx + 33], __float_as_int(fmaxf(v3 + sSh[co], 0.f)));
        }
        __syncthreads();
        int* gout = (int*)out;
        for (int i = tid; i < 512; i += 128) {
            int co = i >> 6, w = i & 63;
            atomicMax(&gout[(b * MIDC + co0 + co) * WW + w0 + w], sMax[co][w]);
        }
    } else {
#pragma unroll
        for (int co = 0; co < 8; co++) {
            float v0, v1, v2, v3;
            unpack2(acc[co][0], v0, v1);
            unpack2(acc[co][1], v2, v3);
            float m = fmaxf(fmaxf(v0, v1), fmaxf(v2, v3));
            atomicMax(&sMax[co][yy], __float_as_int(fmaxf(m + sSh[co], 0.f)));
        }
        __syncthreads();
        int* gout = (int*)out;
        if (tid < 64) {
            int co = tid >> 3, h = tid & 7;
            atomicMax(&gout[(b * MIDC + co0 + co) * HH + h0 + h], sMax[co][h]);
        }
    }
}

// Fused merge: r = relu( bn_p(conv3x3(s)) + bn_c1(conv1x1(x)) ),
// s[b,c,h,w] = colmax[b,c,w] + rowmax[b,c,h] (0 outside bounds).
__global__ __launch_bounds__(128, 4)
void merge_kernel(const float* __restrict__ x,
                  const float* __restrict__ pw, const float* __restrict__ pg,
                  const float* __restrict__ pb, const float* __restrict__ pm,
                  const float* __restrict__ pv,
                  const float* __restrict__ c1w, const float* __restrict__ c1g,
                  const float* __restrict__ c1b, const float* __restrict__ c1m,
                  const float* __restrict__ c1v)
{
    __shared__ float sA[2][4][8][64];       // phase A x tiles
    __shared__ float sS[4][10][66];         // phase B s tile (built in smem)
    __shared__ float sCmRaw[2][4][66];
    __shared__ float sRmRaw[2][4][10];
    __shared__ float sWrawA[2][32];
    __shared__ float sWrawB[2][288];
    __shared__ u64 sW1[8][4];
    __shared__ ulonglong2 sWp[8][4][3];
    __shared__ u64 sW2[8][4][3];
    __shared__ float sScP[8], sScC[8], sSh[8];

    const int wt = blockIdx.x & 1, ht = blockIdx.x >> 1;
    const int w0 = wt * 64, h0 = ht * 8;
    const int co0 = blockIdx.y * 8;
    const int b = blockIdx.z;
    const int xx = threadIdx.x, yy = threadIdx.y;
    const int tid = yy * 16 + xx;

    if (tid < 8) {
        int c = co0 + tid;
        float scp = pg[c] * rsqrtf(pv[c] + EPSV);
        float scc = c1g[c] * rsqrtf(c1v[c] + EPSV);
        sScP[tid] = scp;
        sScC[tid] = scc;
        sSh[tid] = (pb[c] - pm[c] * scp) + (c1b[c] - c1m[c] * scc);
    }

    u64 acc[8][2];
#pragma unroll
    for (int co = 0; co < 8; co++) { acc[co][0] = 0ULL; acc[co][1] = 0ULL; }

    // ---- Phase A: 1x1 conv over x ----
    const float* xb = x + (size_t)b * DIMC * HH * WW;
    auto stageA = [&](int buf, int ci0) {
        for (int idx = tid; idx < 512; idx += 128) {
            int ci = idx >> 7, r = idx & 127;
            int hh = r >> 4, w4 = (r & 15) << 2;
            cp16(smem_u32(&sA[buf][ci][hh][w4]),
                 xb + (size_t)(ci0 + ci) * HH * WW + (h0 + hh) * WW + w0 + w4);
        }
        if (tid < 8)
            cp16(smem_u32(&sWrawA[buf][tid * 4]),
                 c1w + (size_t)(co0 + tid) * DIMC + ci0);
    };

    stageA(0, 0);
    cp_commit();
    for (int ch = 0; ch < DIMC / 4; ch++) {
        int buf = ch & 1;
        cp_wait0();
        __syncthreads();
        if (ch + 1 < DIMC / 4) { stageA(buf ^ 1, (ch + 1) * 4); cp_commit(); }
        if (tid < 32) {
            int co = tid >> 2, ci = tid & 3;
            float w = sWrawA[buf][co * 4 + ci] * sScC[co];
            sW1[co][ci] = pack2(w, w);
        }
        __syncthreads();
        for (int ci = 0; ci < 4; ci++) {
            const float* row = &sA[buf][ci][yy][0];
            u64 A = *(const u64*)(row + 2 * xx);
            u64 B = *(const u64*)(row + 2 * xx + 32);
#pragma unroll
            for (int co = 0; co < 8; co++) {
                u64 wv = sW1[co][ci];
                fma2(acc[co][0], wv, A);
                fma2(acc[co][1], wv, B);
            }
        }
    }

    // ---- Phase B: 3x3 conv over s ----
    auto stageB = [&](int buf, int ci0) {
        for (int idx = tid; idx < 264; idx += 128) {
            int ci = idx / 66, c = idx % 66;
            int gw = w0 - 1 + c;
            bool valid = (unsigned)gw < (unsigned)WW;
            cp4(smem_u32(&sCmRaw[buf][ci][c]),
                g_colmax + (b * MIDC + ci0 + ci) * WW + (valid ? gw : 0), valid);
        }
        if (tid < 40) {
            int ci = tid / 10, hh = tid % 10;
            int gh = h0 - 1 + hh;
            bool valid = (unsigned)gh < (unsigned)HH;
            cp4(smem_u32(&sRmRaw[buf][ci][hh]),
                g_rowmax + (b * MIDC + ci0 + ci) * HH + (valid ? gh : 0), valid);
        }
        if (tid < 72) {
            int co = tid / 9, q = tid % 9;
            cp16(smem_u32(&sWrawB[buf][co * 36 + q * 4]),
                 pw + ((size_t)(co0 + co) * MIDC + ci0) * 9 + q * 4);
        }
    };

    stageB(0, 0);
    cp_commit();
    for (int ch = 0; ch < MIDC / 4; ch++) {
        int buf = ch & 1;
        cp_wait0();
        __syncthreads();
        if (ch + 1 < MIDC / 4) { stageB(buf ^ 1, (ch + 1) * 4); cp_commit(); }

        // expand weights
        for (int idx = tid; idx < 288; idx += 128) {
            int co = idx / 36, r = idx % 36, ci = r / 9, k = r % 9;
            int dy = k / 3, dx = k % 3;
            float w = sWrawB[buf][idx] * sScP[co];
            u64 d = pack2(w, w);
            if (dx == 2) sW2[co][ci][dy] = d;
            else ((u64*)&sWp[co][ci][dy])[dx] = d;
        }
        // build s tile (boundary zeros: either coord OOB -> 0)
        for (int idx = tid; idx < 2640; idx += 128) {
            int ci = idx / 660, r = idx % 660;
            int hh = r / 66, c = r % 66;
            bool v = ((unsigned)(h0 + hh - 1) < (unsigned)HH) &&
                     ((unsigned)(w0 + c - 1) < (unsigned)WW);
            float s = v ? (sCmRaw[buf][ci][c] + sRmRaw[buf][ci][hh]) : 0.f;
            ((float*)sS)[idx] = s;
        }
        __syncthreads();

        for (int ci = 0; ci < 4; ci++) {
#pragma unroll
            for (int dy = 0; dy < 3; dy++) {
                const float* row = &sS[ci][yy + dy][0];
                u64 P0 = *(const u64*)(row + 2 * xx);
                u64 P2 = *(const u64*)(row + 2 * xx + 2);
                u64 Q0 = *(const u64*)(row + 2 * xx + 32);
                u64 Q2 = *(const u64*)(row + 2 * xx + 34);
                float p0l, p0h, p2l, p2h, q0l, q0h, q2l, q2h;
                unpack2(P0, p0l, p0h); unpack2(P2, p2l, p2h);
                unpack2(Q0, q0l, q0h); unpack2(Q2, q2l, q2h);
                u64 P1 = pack2(p0h, p2l);
                u64 Q1 = pack2(q0h, q2l);
#pragma unroll
                for (int co = 0; co < 8; co++) {
                    ulonglong2 wp = sWp[co][ci][dy];
                    u64 w2v = sW2[co][ci][dy];
                    fma2(acc[co][0], wp.x, P0);
                    fma2(acc[co][1], wp.x, Q0);
                    fma2(acc[co][0], wp.y, P1);
                    fma2(acc[co][1], wp.y, Q1);
                    fma2(acc[co][0], w2v, P2);
                    fma2(acc[co][1], w2v, Q2);
                }
            }
        }
        __syncthreads();   // protect sS reuse next chunk
    }

    // epilogue
#pragma unroll
    for (int co = 0; co < 8; co++) {
        float v0, v1, v2, v3;
        unpack2(acc[co][0], v0, v1);
        unpack2(acc[co][1], v2, v3);
        float2 oA, oB;
        oA.x = fmaxf(v0 + sSh[co], 0.f); oA.y = fmaxf(v1 + sSh[co], 0.f);
        oB.x = fmaxf(v2 + sSh[co], 0.f); oB.y = fmaxf(v3 + sSh[co], 0.f);
        float* op = &g_r[((size_t)(b * DIMC + co0 + co) * HH + h0 + yy) * WW + w0];
        *(float2*)(op + 2 * xx) = oA;
        *(float2*)(op + 2 * xx + 32) = oB;
    }
}

extern "C" void kernel_launch(void* const* d_in, const int* in_sizes, int n_in,
                              void* d_out, int out_size)
{
    const float* x    = (const float*)d_in[0];
    const float* p1w  = (const float*)d_in[1];
    const float* p1g  = (const float*)d_in[2];
    const float* p1b  = (const float*)d_in[3];
    const float* p1m  = (const float*)d_in[4];
    const float* p1v  = (const float*)d_in[5];
    const float* p2w  = (const float*)d_in[6];
    const float* p2g  = (const float*)d_in[7];
    const float* p2b  = (const float*)d_in[8];
    const float* p2m  = (const float*)d_in[9];
    const float* p2v  = (const float*)d_in[10];
    const float* pw   = (const float*)d_in[11];
    const float* pg   = (const float*)d_in[12];
    const float* pb   = (const float*)d_in[13];
    const float* pm   = (const float*)d_in[14];
    const float* pv   = (const float*)d_in[15];
    const float* c1w  = (const float*)d_in[16];
    const float* c1g  = (const float*)d_in[17];
    const float* c1b  = (const float*)d_in[18];
    const float* c1m  = (const float*)d_in[19];
    const float* c1v  = (const float*)d_in[20];
    const float* c2w  = (const float*)d_in[21];
    const float* c2g  = (const float*)d_in[22];
    const float* c2b  = (const float*)d_in[23];
    const float* c2m  = (const float*)d_in[24];
    const float* c2v  = (const float*)d_in[25];

    float* colmax;  cudaGetSymbolAddress((void**)&colmax, g_colmax);
    float* rowmax;  cudaGetSymbolAddress((void**)&rowmax, g_rowmax);
    float* rbuf;    cudaGetSymbolAddress((void**)&rbuf, g_r);

    dim3 blk(16, 8);

    init_max_kernel<<<256, 256>>>();

    conv3_kernel<<<dim3(32, MIDC / 8, BATCH), blk>>>(
        x, p1w, p1g, p1b, p1m, p1v, DIMC, MIDC, 0, colmax);

    conv3_kernel<<<dim3(32, MIDC / 8, BATCH), blk>>>(
        x, p2w, p2g, p2b, p2m, p2v, DIMC, MIDC, 1, rowmax);

    merge_kernel<<<dim3(32, DIMC / 8, BATCH), blk>>>(
        x, pw, pg, pb, pm, pv, c1w, c1g, c1b, c1m, c1v);

    conv3_kernel<<<dim3(32, DIMC / 8, BATCH), blk>>>(
        rbuf, c2w, c2g, c2b, c2m, c2v, DIMC, DIMC, 2, (float*)d_out);
}